// round 8
// baseline (speedup 1.0000x reference)
#include <cuda_runtime.h>
#include <cuda_bf16.h>
#include <cstdint>

#define NN 50000
#define NE 800000
#define NB 49   // ceil(NN/1024)

// ---------------- scratch (static device globals; no allocation) ----------------
__device__ __align__(16) float g_buf1[NN * 256];  // zx (N,128) -> h2 (N,128)
__device__ __align__(16) float g_buf2[NN * 256];  // h (N,256) -> h_emb (N,128)
__device__ __align__(16) float4 g_proj[NN];       // per-node edge projections
__device__ float g_dinv[NN];
__device__ int   g_deg[NN];
__device__ int   g_cur[NN];
__device__ int   g_off[NN + 1];
__device__ int   g_bsum[NB];
__device__ int   g_srcs[NE];
__device__ float g_gacc[128];

// ---------------- setup ----------------
__global__ void deg_kernel(const int* __restrict__ dst) {
    int e = blockIdx.x * blockDim.x + threadIdx.x;
    if (e < NE) atomicAdd(&g_deg[dst[e]], 1);
}

__global__ __launch_bounds__(1024) void scan1_kernel() {
    __shared__ int wsum[32];
    int i = blockIdx.x * 1024 + threadIdx.x;
    int d = (i < NN) ? g_deg[i] : 0;
    if (i < NN) g_dinv[i] = rsqrtf((float)(d + 1));
    int lane = threadIdx.x & 31, w = threadIdx.x >> 5;
    int v = d;
#pragma unroll
    for (int o = 1; o < 32; o <<= 1) {
        int t = __shfl_up_sync(0xffffffffu, v, o);
        if (lane >= o) v += t;
    }
    if (lane == 31) wsum[w] = v;
    __syncthreads();
    if (w == 0) {
        int s = wsum[lane];
#pragma unroll
        for (int o = 1; o < 32; o <<= 1) {
            int t = __shfl_up_sync(0xffffffffu, s, o);
            if (lane >= o) s += t;
        }
        wsum[lane] = s;
    }
    __syncthreads();
    int excl = v - d + (w > 0 ? wsum[w - 1] : 0);
    if (i < NN) g_off[i] = excl;
    if (threadIdx.x == 1023) g_bsum[blockIdx.x] = wsum[31];
}

__global__ __launch_bounds__(1024) void scan2_kernel() {
    __shared__ int red[2];
    int t = threadIdx.x;
    if (t < 64) {
        int v = (t < blockIdx.x) ? g_bsum[t] : 0;
#pragma unroll
        for (int o = 16; o > 0; o >>= 1) v += __shfl_down_sync(0xffffffffu, v, o);
        if ((t & 31) == 0) red[t >> 5] = v;
    }
    __syncthreads();
    int base = red[0] + red[1];
    int i = blockIdx.x * 1024 + t;
    if (i < NN) g_off[i] += base;
    if (blockIdx.x == 0 && t == 0) g_off[NN] = NE;
}

__global__ void fill_kernel(const int* __restrict__ src, const int* __restrict__ dst) {
    int e = blockIdx.x * blockDim.x + threadIdx.x;
    if (e < NE) {
        int d = dst[e];
        int p = atomicAdd(&g_cur[d], 1);
        g_srcs[g_off[d] + p] = src[e];
    }
}

// ---------------- layer-1 pre-aggregation on x (128-dim), warp per node ----------------
__global__ __launch_bounds__(256) void aggx_kernel(const float* __restrict__ x,
                                                   float* __restrict__ z)
{
    int warp = (blockIdx.x * 256 + threadIdx.x) >> 5;
    int lane = threadIdx.x & 31;
    if (warp >= NN) return;
    const float4* __restrict__ X = (const float4*)x;
    int d = warp;
    float dd = g_dinv[d];
    int e0 = g_off[d], e1 = g_off[d + 1];
    float4 acc = make_float4(0.f, 0.f, 0.f, 0.f);
    for (int e = e0; e < e1; e++) {
        int s = g_srcs[e];
        float nm = g_dinv[s] * dd;
        float4 v = X[(size_t)s * 32 + lane];
        acc.x = fmaf(v.x, nm, acc.x); acc.y = fmaf(v.y, nm, acc.y);
        acc.z = fmaf(v.z, nm, acc.z); acc.w = fmaf(v.w, nm, acc.w);
    }
    float sn = dd * dd;
    float4 v = X[(size_t)d * 32 + lane];
    acc.x = fmaf(v.x, sn, acc.x); acc.y = fmaf(v.y, sn, acc.y);
    acc.z = fmaf(v.z, sn, acc.z); acc.w = fmaf(v.w, sn, acc.w);
    ((float4*)z)[(size_t)d * 32 + lane] = acc;
}

// ================ bf16 split mma.sync GEMM (sm_80+ path, tensor pipe) ================
// C[M,N] = op(A[M,K] @ B[K,N] (+bias)). Block tile 128x128; grid (N/128, ceil(M/128)).
// 8 warps as 2(M)x4(N); each warp 64x32. bf16 2-way split, 3 products/k-chunk of 16.

__device__ __forceinline__ void mma16816(float* d, const uint32_t* a, const uint32_t* b) {
    asm volatile(
        "mma.sync.aligned.m16n8k16.row.col.f32.bf16.bf16.f32 "
        "{%0,%1,%2,%3}, {%4,%5,%6,%7}, {%8,%9}, {%0,%1,%2,%3};"
        : "+f"(d[0]), "+f"(d[1]), "+f"(d[2]), "+f"(d[3])
        : "r"(a[0]), "r"(a[1]), "r"(a[2]), "r"(a[3]), "r"(b[0]), "r"(b[1]));
}

__device__ __forceinline__ uint32_t pack_hi(float x, float y,
                                            __nv_bfloat16& hx, __nv_bfloat16& hy) {
    hx = __float2bfloat16(x);
    hy = __float2bfloat16(y);
    __nv_bfloat162 p; p.x = hx; p.y = hy;
    return *(uint32_t*)&p;
}
__device__ __forceinline__ uint32_t pack_lo(float x, float y,
                                            __nv_bfloat16 hx, __nv_bfloat16 hy) {
    __nv_bfloat162 p;
    p.x = __float2bfloat16(x - __bfloat162float(hx));
    p.y = __float2bfloat16(y - __bfloat162float(hy));
    return *(uint32_t*)&p;
}

#define SPAD 136   // u32 row stride: (kpair*136 + idx) mod 32 = kpair*8 + idx -> conflict-free frags

__global__ __launch_bounds__(256) void mma_gemm_kernel(
    const float* __restrict__ A, const float* __restrict__ B, float* __restrict__ C,
    const float* __restrict__ bias, int relu, int M, int N, int K)
{
    __shared__ uint32_t As2h[8][SPAD];
    __shared__ uint32_t As2l[8][SPAD];
    __shared__ uint32_t Bs2h[8][SPAD];
    __shared__ uint32_t Bs2l[8][SPAD];

    const int tid = threadIdx.x;
    const int w = tid >> 5;
    const int l = tid & 31;
    const int m0 = blockIdx.y * 128;
    const int n0 = blockIdx.x * 128;
    const int mwarp = (w & 1) * 64;
    const int nwarp = (w >> 1) * 32;
    const int lq = l >> 2;    // 0..7
    const int lr = l & 3;     // 0..3

    float d[4][4][4];
#pragma unroll
    for (int mt = 0; mt < 4; mt++)
#pragma unroll
        for (int nt = 0; nt < 4; nt++)
#pragma unroll
            for (int i = 0; i < 4; i++) d[mt][nt][i] = 0.f;

    const int nch = K >> 4;
    for (int ch = 0; ch < nch; ch++) {
        // ---- A chunk: 128 rows x 16 k (fp32 float4 over k), split into hi/lo bf16x2 ----
#pragma unroll
        for (int s = tid; s < 512; s += 256) {
            int m = s >> 2, kq = s & 3;
            int gm = m0 + m;
            float4 v = make_float4(0.f, 0.f, 0.f, 0.f);
            if (gm < M) v = *(const float4*)(A + (size_t)gm * K + ch * 16 + kq * 4);
            __nv_bfloat16 hx, hy, hz, hw;
            uint32_t h0 = pack_hi(v.x, v.y, hx, hy);
            uint32_t h1 = pack_hi(v.z, v.w, hz, hw);
            As2h[kq * 2 + 0][m] = h0;
            As2h[kq * 2 + 1][m] = h1;
            As2l[kq * 2 + 0][m] = pack_lo(v.x, v.y, hx, hy);
            As2l[kq * 2 + 1][m] = pack_lo(v.z, v.w, hz, hw);
        }
        // ---- B chunk: 16 k-rows x 128 n, 16-bit stores into [kpair][n] words ----
#pragma unroll
        for (int i = tid; i < 2048; i += 256) {
            int k = i >> 7, n = i & 127;
            float v = B[(size_t)(ch * 16 + k) * N + n0 + n];
            __nv_bfloat16 h = __float2bfloat16(v);
            __nv_bfloat16 lo = __float2bfloat16(v - __bfloat162float(h));
            uint32_t off = ((uint32_t)(k >> 1) * SPAD + n) * 4 + (k & 1) * 2;
            *(__nv_bfloat16*)((char*)Bs2h + off) = h;
            *(__nv_bfloat16*)((char*)Bs2l + off) = lo;
        }
        __syncthreads();

        // ---- b fragments (k16 x n8), hi+lo ----
        uint32_t bh[4][2], bl[4][2];
#pragma unroll
        for (int nt = 0; nt < 4; nt++) {
            int n = nwarp + nt * 8 + lq;
            bh[nt][0] = Bs2h[lr][n];     bh[nt][1] = Bs2h[lr + 4][n];
            bl[nt][0] = Bs2l[lr][n];     bl[nt][1] = Bs2l[lr + 4][n];
        }
#pragma unroll
        for (int mt = 0; mt < 4; mt++) {
            int mb = mwarp + mt * 16;
            uint32_t ah[4], al[4];
            ah[0] = As2h[lr][mb + lq];       ah[1] = As2h[lr][mb + lq + 8];
            ah[2] = As2h[lr + 4][mb + lq];   ah[3] = As2h[lr + 4][mb + lq + 8];
            al[0] = As2l[lr][mb + lq];       al[1] = As2l[lr][mb + lq + 8];
            al[2] = As2l[lr + 4][mb + lq];   al[3] = As2l[lr + 4][mb + lq + 8];
#pragma unroll
            for (int nt = 0; nt < 4; nt++) {
                mma16816(d[mt][nt], ah, bh[nt]);
                mma16816(d[mt][nt], ah, bl[nt]);
                mma16816(d[mt][nt], al, bh[nt]);
            }
        }
        __syncthreads();
    }

    // ---- epilogue ----
#pragma unroll
    for (int mt = 0; mt < 4; mt++) {
#pragma unroll
        for (int nt = 0; nt < 4; nt++) {
            int col = n0 + nwarp + nt * 8 + lr * 2;
            float bx = 0.f, by = 0.f;
            if (bias) { bx = bias[col]; by = bias[col + 1]; }
            int row0 = m0 + mwarp + mt * 16 + lq;
            float e0 = d[mt][nt][0] + bx, e1 = d[mt][nt][1] + by;
            float e2 = d[mt][nt][2] + bx, e3 = d[mt][nt][3] + by;
            if (relu) {
                e0 = fmaxf(e0, 0.f); e1 = fmaxf(e1, 0.f);
                e2 = fmaxf(e2, 0.f); e3 = fmaxf(e3, 0.f);
            }
            if (row0 < M) *(float2*)(C + (size_t)row0 * N + col) = make_float2(e0, e1);
            int row1 = row0 + 8;
            if (row1 < M) *(float2*)(C + (size_t)row1 * N + col) = make_float2(e2, e3);
        }
    }
}

// ---------------- layer-2 aggregation fused with node_logits + edge projections + mean ----------------
__global__ __launch_bounds__(256) void agg2_fused_kernel(
    const float* __restrict__ h2, const float* __restrict__ bias,
    const float* __restrict__ npW, const float* __restrict__ npb,
    const float* __restrict__ epW,
    float* __restrict__ hemb, float* __restrict__ node_logits)
{
    __shared__ float gsum[128];
    const int tid = threadIdx.x;
    if (tid < 128) gsum[tid] = 0.f;
    __syncthreads();

    const int lane = tid & 31;
    int warp = (blockIdx.x * blockDim.x + tid) >> 5;
    const int nw = (gridDim.x * blockDim.x) >> 5;
    const int k = lane * 4;

    float w0[4], w1[4], w2[4];
    float es0[4], es1[4], ed0[4], ed1[4];
#pragma unroll
    for (int j = 0; j < 4; j++) {
        w0[j] = npW[(k + j) * 3 + 0];
        w1[j] = npW[(k + j) * 3 + 1];
        w2[j] = npW[(k + j) * 3 + 2];
        es0[j] = epW[(k + j) * 2 + 0];
        es1[j] = epW[(k + j) * 2 + 1];
        ed0[j] = epW[(128 + k + j) * 2 + 0];
        ed1[j] = epW[(128 + k + j) * 2 + 1];
    }
    float nb0 = npb[0], nb1 = npb[1], nb2 = npb[2];
    float4 bs = ((const float4*)bias)[lane];
    float gl0 = 0.f, gl1 = 0.f, gl2 = 0.f, gl3 = 0.f;
    const float4* __restrict__ H = (const float4*)h2;

    for (int d = warp; d < NN; d += nw) {
        float dd = g_dinv[d];
        int e0 = g_off[d], e1 = g_off[d + 1];
        float4 acc = make_float4(0.f, 0.f, 0.f, 0.f);
        for (int e = e0; e < e1; e++) {
            int s = g_srcs[e];
            float nm = g_dinv[s] * dd;
            float4 v = H[(size_t)s * 32 + lane];
            acc.x = fmaf(v.x, nm, acc.x); acc.y = fmaf(v.y, nm, acc.y);
            acc.z = fmaf(v.z, nm, acc.z); acc.w = fmaf(v.w, nm, acc.w);
        }
        float sn = dd * dd;
        float4 v = H[(size_t)d * 32 + lane];
        acc.x = fmaf(v.x, sn, acc.x); acc.y = fmaf(v.y, sn, acc.y);
        acc.z = fmaf(v.z, sn, acc.z); acc.w = fmaf(v.w, sn, acc.w);
        acc.x = fmaxf(acc.x + bs.x, 0.f); acc.y = fmaxf(acc.y + bs.y, 0.f);
        acc.z = fmaxf(acc.z + bs.z, 0.f); acc.w = fmaxf(acc.w + bs.w, 0.f);
        ((float4*)hemb)[(size_t)d * 32 + lane] = acc;

        gl0 += acc.x; gl1 += acc.y; gl2 += acc.z; gl3 += acc.w;

        float l0 = acc.x * w0[0] + acc.y * w0[1] + acc.z * w0[2] + acc.w * w0[3];
        float l1 = acc.x * w1[0] + acc.y * w1[1] + acc.z * w1[2] + acc.w * w1[3];
        float l2 = acc.x * w2[0] + acc.y * w2[1] + acc.z * w2[2] + acc.w * w2[3];
        float p0 = acc.x * es0[0] + acc.y * es0[1] + acc.z * es0[2] + acc.w * es0[3];
        float p1 = acc.x * es1[0] + acc.y * es1[1] + acc.z * es1[2] + acc.w * es1[3];
        float q0 = acc.x * ed0[0] + acc.y * ed0[1] + acc.z * ed0[2] + acc.w * ed0[3];
        float q1 = acc.x * ed1[0] + acc.y * ed1[1] + acc.z * ed1[2] + acc.w * ed1[3];
#pragma unroll
        for (int o = 16; o > 0; o >>= 1) {
            l0 += __shfl_down_sync(0xffffffffu, l0, o);
            l1 += __shfl_down_sync(0xffffffffu, l1, o);
            l2 += __shfl_down_sync(0xffffffffu, l2, o);
            p0 += __shfl_down_sync(0xffffffffu, p0, o);
            p1 += __shfl_down_sync(0xffffffffu, p1, o);
            q0 += __shfl_down_sync(0xffffffffu, q0, o);
            q1 += __shfl_down_sync(0xffffffffu, q1, o);
        }
        if (lane == 0) {
            node_logits[(size_t)d * 3 + 0] = l0 + nb0;
            node_logits[(size_t)d * 3 + 1] = l1 + nb1;
            node_logits[(size_t)d * 3 + 2] = l2 + nb2;
            g_proj[d] = make_float4(p0, p1, q0, q1);
        }
    }
    atomicAdd(&gsum[k + 0], gl0);
    atomicAdd(&gsum[k + 1], gl1);
    atomicAdd(&gsum[k + 2], gl2);
    atomicAdd(&gsum[k + 3], gl3);
    __syncthreads();
    if (tid < 128) atomicAdd(&g_gacc[tid], gsum[tid]);
}

// ---------------- edge head via per-node projections ----------------
__global__ __launch_bounds__(256) void edge2_kernel(
    const int* __restrict__ src, const int* __restrict__ dst,
    const float* __restrict__ epb, float* __restrict__ out)
{
    int e = blockIdx.x * blockDim.x + threadIdx.x;
    if (e >= NE) return;
    float4 a = g_proj[src[e]];
    float4 b = g_proj[dst[e]];
    float2 r;
    r.x = a.x + b.z + epb[0];
    r.y = a.y + b.w + epb[1];
    *(float2*)(out + (size_t)e * 2) = r;
}

// ---------------- tiny global heads ----------------
__global__ __launch_bounds__(256) void head_kernel(
    const float* __restrict__ fc1W, const float* __restrict__ fc1b,
    const float* __restrict__ fc2W, const float* __restrict__ fc2b,
    const float* __restrict__ gpW, const float* __restrict__ gpb,
    float* __restrict__ out_glob, float* __restrict__ out_value)
{
    __shared__ float g[128];
    __shared__ float vsh[256];
    __shared__ float red[8];
    const int t = threadIdx.x;
    const int lane = t & 31, wid = t >> 5;
    if (t < 128) g[t] = g_gacc[t] * (1.0f / (float)NN);
    __syncthreads();

    float acc = 0.f;
    for (int kk = 0; kk < 128; kk++) acc = fmaf(g[kk], fc1W[kk * 256 + t], acc);
    vsh[t] = fmaxf(acc + fc1b[t], 0.f);
    __syncthreads();

    float p = vsh[t] * fc2W[t];
#pragma unroll
    for (int o = 16; o > 0; o >>= 1) p += __shfl_down_sync(0xffffffffu, p, o);
    if (lane == 0) red[wid] = p;
    __syncthreads();
    if (t == 0) {
        float tot = 0.f;
        for (int i = 0; i < 8; i++) tot += red[i];
        out_value[0] = tot + fc2b[0];
    }
    __syncthreads();

    float q = (t < 128) ? g[t] * gpW[t] : 0.f;
#pragma unroll
    for (int o = 16; o > 0; o >>= 1) q += __shfl_down_sync(0xffffffffu, q, o);
    if (lane == 0) red[wid] = q;
    __syncthreads();
    if (t == 0) {
        float tot = 0.f;
        for (int i = 0; i < 8; i++) tot += red[i];
        out_glob[0] = tot + gpb[0];
    }
}

// ---------------- launch ----------------
extern "C" void kernel_launch(void* const* d_in, const int* in_sizes, int n_in,
                              void* d_out, int out_size)
{
    const float* x    = (const float*)d_in[0];
    const int*   ei   = (const int*)d_in[1];
    const float* W1   = (const float*)d_in[2];
    const float* b1   = (const float*)d_in[3];
    const float* W2   = (const float*)d_in[4];
    const float* b2   = (const float*)d_in[5];
    const float* fc1W = (const float*)d_in[6];
    const float* fc1b = (const float*)d_in[7];
    const float* fc2W = (const float*)d_in[8];
    const float* fc2b = (const float*)d_in[9];
    const float* npW  = (const float*)d_in[10];
    const float* npb  = (const float*)d_in[11];
    const float* epW  = (const float*)d_in[12];
    const float* epb  = (const float*)d_in[13];
    const float* gpW  = (const float*)d_in[14];
    const float* gpb  = (const float*)d_in[15];

    float* out = (float*)d_out;
    float* out_node  = out;
    float* out_edge  = out + (size_t)NN * 3;
    float* out_glob  = out + (size_t)NN * 3 + (size_t)NE * 2;
    float* out_value = out_glob + 1;

    const int* src = ei;
    const int* dst = ei + NE;

    float* buf1; float* buf2;
    void* p;
    cudaGetSymbolAddress(&p, g_buf1); buf1 = (float*)p;
    cudaGetSymbolAddress(&p, g_buf2); buf2 = (float*)p;
    void* pdeg;  cudaGetSymbolAddress(&pdeg, g_deg);
    void* pcur;  cudaGetSymbolAddress(&pcur, g_cur);
    void* pgacc; cudaGetSymbolAddress(&pgacc, g_gacc);

    cudaMemsetAsync(pdeg, 0, NN * sizeof(int));
    cudaMemsetAsync(pcur, 0, NN * sizeof(int));
    cudaMemsetAsync(pgacc, 0, 128 * sizeof(float));

    deg_kernel<<<(NE + 255) / 256, 256>>>(dst);
    scan1_kernel<<<NB, 1024>>>();
    scan2_kernel<<<NB, 1024>>>();
    fill_kernel<<<(NE + 255) / 256, 256>>>(src, dst);

    const int mtiles = (NN + 127) / 128;   // 391

    // zx = A_hat @ x   [N,128]
    aggx_kernel<<<(NN * 32 + 255) / 256, 256>>>(x, buf1);
    // h = relu(zx @ W1 + b1)  [N,256]  — bf16-split tensor-core GEMM
    mma_gemm_kernel<<<dim3(2, mtiles), 256>>>(buf1, W1, buf2, b1, 1, NN, 256, 128);
    // h2 = h @ W2  [N,128]
    mma_gemm_kernel<<<dim3(1, mtiles), 256>>>(buf2, W2, buf1, nullptr, 0, NN, 128, 256);
    // h_emb = relu(agg(h2) + b2); node_logits; edge projections; mean partials
    agg2_fused_kernel<<<1024, 256>>>(buf1, b2, npW, npb, epW, buf2, out_node);
    // edge logits from projections
    edge2_kernel<<<(NE + 255) / 256, 256>>>(src, dst, epb, out_edge);
    // value + global logits
    head_kernel<<<1, 256>>>(fc1W, fc1b, fc2W, fc2b, gpW, gpb, out_glob, out_value);
}